// round 14
// baseline (speedup 1.0000x reference)
#include <cuda_runtime.h>
#include <cuda_bf16.h>
#include <cstdint>
#include <math.h>

#define SEQ   128
#define BAT   32
#define EH    512
#define EO    256
#define HID   512
#define G3    1536
#define OUTD  256
#define MROWS (SEQ*BAT)
#define THRESH 1e-6f

typedef unsigned long long ull;
typedef unsigned int u32;

// ---------------- scratch (device globals; no allocation allowed) ----------
__device__ float g_emb[MROWS * EO];          // 4 MB
__device__ float g_xproj[MROWS * G3];        // 25 MB
__device__ float g_h[2][BAT * HID];          // ping-pong hidden state
// per-CTA barrier flags, 128B apart; monotonic within a launch, reset at end
__device__ __align__(128) unsigned g_bflags[128 * 32];

// ---------------- f32x2 helpers -------------------------------------------
__device__ __forceinline__ ull pack2(float lo, float hi) {
    ull r; asm("mov.b64 %0, {%1, %2};" : "=l"(r) : "f"(lo), "f"(hi)); return r;
}
__device__ __forceinline__ float2 unpack2(ull v) {
    float2 r; asm("mov.b64 {%0, %1}, %2;" : "=f"(r.x), "=f"(r.y) : "l"(v)); return r;
}
__device__ __forceinline__ void fma2(ull& d, ull a, ull b) {
    asm("fma.rn.f32x2 %0, %1, %2, %3;" : "=l"(d) : "l"(a), "l"(b), "l"(d));
}
__device__ __forceinline__ float thr(float v) { return v > THRESH ? v : 0.0f; }

// fast gates: MUFU-based sigmoid / tanh
__device__ __forceinline__ float fast_sigmoid(float x) {
    float e = __expf(-x);
    return __fdividef(1.0f, 1.0f + e);
}
__device__ __forceinline__ float fast_tanh(float x) {
    float e = __expf(-2.0f * x);
    return __fdividef(1.0f - e, 1.0f + e);
}

// ---------------- acquire/release helpers (GPU scope, L2) ------------------
__device__ __forceinline__ unsigned ld_acq(const unsigned* p) {
    unsigned v; asm volatile("ld.acquire.gpu.u32 %0, [%1];" : "=r"(v) : "l"(p)); return v;
}
__device__ __forceinline__ void st_rel(unsigned* p, unsigned v) {
    asm volatile("st.release.gpu.u32 [%0], %1;" :: "l"(p), "r"(v));
}
// ---------------- acquire/release helpers (CTA scope, SMEM) ----------------
__device__ __forceinline__ u32 smem_u32(const void* p) {
    u32 a;
    asm("{ .reg .u64 t; cvta.to.shared.u64 t, %1; cvt.u32.u64 %0, t; }"
        : "=r"(a) : "l"(p));
    return a;
}
__device__ __forceinline__ unsigned ld_acq_sh(u32 addr) {
    unsigned v; asm volatile("ld.acquire.cta.shared.u32 %0, [%1];" : "=r"(v) : "r"(addr)); return v;
}
__device__ __forceinline__ void st_rel_sh(u32 addr, unsigned v) {
    asm volatile("st.release.cta.shared.u32 [%0], %1;" :: "r"(addr), "r"(v));
}

// ===========================================================================
// GEMM 1 (fused embedding): emb = thr( thr(W1[tok]+b1) @ W2 + b2 )
// ===========================================================================
__global__ __launch_bounds__(256) void gemm_embed_kernel(
    const int* __restrict__ tok, const float* __restrict__ W1,
    const float* __restrict__ b1, const float* __restrict__ W2,
    const float* __restrict__ b2)
{
    __shared__ __align__(16) float As[16][132];
    __shared__ __align__(16) float Bs[16][68];

    const int bm = blockIdx.x, bn = blockIdx.y;
    const int t  = threadIdx.x;
    const int tx = t & 15, ty = t >> 4;

    const int arow = t >> 2, aseg = t & 3;
    const int tk0 = tok[bm * 128 + arow];
    const int tk1 = tok[bm * 128 + arow + 64];
    const float* w1r0 = W1 + (size_t)tk0 * EH;
    const float* w1r1 = W1 + (size_t)tk1 * EH;
    const int bk = t >> 4, bseg = t & 15;

    ull acc[8][2] = {};

    for (int kt = 0; kt < EH; kt += 16) {
        float4 bb = *(const float4*)(b1 + kt + aseg * 4);
        float4 a0 = *(const float4*)(w1r0 + kt + aseg * 4);
        float4 a1 = *(const float4*)(w1r1 + kt + aseg * 4);
        a0.x = thr(a0.x + bb.x); a0.y = thr(a0.y + bb.y);
        a0.z = thr(a0.z + bb.z); a0.w = thr(a0.w + bb.w);
        a1.x = thr(a1.x + bb.x); a1.y = thr(a1.y + bb.y);
        a1.z = thr(a1.z + bb.z); a1.w = thr(a1.w + bb.w);
        As[aseg * 4 + 0][arow] = a0.x;  As[aseg * 4 + 0][arow + 64] = a1.x;
        As[aseg * 4 + 1][arow] = a0.y;  As[aseg * 4 + 1][arow + 64] = a1.y;
        As[aseg * 4 + 2][arow] = a0.z;  As[aseg * 4 + 2][arow + 64] = a1.z;
        As[aseg * 4 + 3][arow] = a0.w;  As[aseg * 4 + 3][arow + 64] = a1.w;
        *(float4*)&Bs[bk][bseg * 4] =
            *(const float4*)(W2 + (size_t)(kt + bk) * EO + bn * 64 + bseg * 4);
        __syncthreads();
        #pragma unroll
        for (int kk = 0; kk < 16; kk++) {
            float4 av0 = *(const float4*)&As[kk][ty * 8];
            float4 av1 = *(const float4*)&As[kk][ty * 8 + 4];
            ulonglong2 bv = *(const ulonglong2*)&Bs[kk][tx * 4];
            ull a;
            a = pack2(av0.x, av0.x); fma2(acc[0][0], a, bv.x); fma2(acc[0][1], a, bv.y);
            a = pack2(av0.y, av0.y); fma2(acc[1][0], a, bv.x); fma2(acc[1][1], a, bv.y);
            a = pack2(av0.z, av0.z); fma2(acc[2][0], a, bv.x); fma2(acc[2][1], a, bv.y);
            a = pack2(av0.w, av0.w); fma2(acc[3][0], a, bv.x); fma2(acc[3][1], a, bv.y);
            a = pack2(av1.x, av1.x); fma2(acc[4][0], a, bv.x); fma2(acc[4][1], a, bv.y);
            a = pack2(av1.y, av1.y); fma2(acc[5][0], a, bv.x); fma2(acc[5][1], a, bv.y);
            a = pack2(av1.z, av1.z); fma2(acc[6][0], a, bv.x); fma2(acc[6][1], a, bv.y);
            a = pack2(av1.w, av1.w); fma2(acc[7][0], a, bv.x); fma2(acc[7][1], a, bv.y);
        }
        __syncthreads();
    }
    const int m0 = bm * 128 + ty * 8, n0 = bn * 64 + tx * 4;
    #pragma unroll
    for (int i = 0; i < 8; i++) {
        #pragma unroll
        for (int p = 0; p < 2; p++) {
            float2 v = unpack2(acc[i][p]);
            int n = n0 + p * 2;
            v.x = thr(v.x + b2[n]);
            v.y = thr(v.y + b2[n + 1]);
            *(float2*)&g_emb[(size_t)(m0 + i) * EO + n] = v;
        }
    }
}

// ===========================================================================
// GEMM 2 (NT): xproj = emb @ W_ih^T + b_ih   (two N-half launches)
// ===========================================================================
__global__ __launch_bounds__(256) void gemm_xproj_kernel(
    const float* __restrict__ W_ih, const float* __restrict__ b_ih,
    int bn_off)
{
    __shared__ __align__(16) float As[16][132];
    __shared__ __align__(16) float Bs[16][132];

    const int bm = blockIdx.x, bn = blockIdx.y + bn_off;
    const int t  = threadIdx.x;
    const int tx = t & 15, ty = t >> 4;
    const int row = t >> 2, seg = t & 3;

    ull acc[8][4] = {};

    for (int kt = 0; kt < EO; kt += 16) {
        #pragma unroll
        for (int i = 0; i < 2; i++) {
            int r = row + i * 64;
            float4 a4 = *(const float4*)(g_emb + (size_t)(bm * 128 + r) * EO + kt + seg * 4);
            As[seg * 4 + 0][r] = a4.x;
            As[seg * 4 + 1][r] = a4.y;
            As[seg * 4 + 2][r] = a4.z;
            As[seg * 4 + 3][r] = a4.w;
            float4 b4 = *(const float4*)(W_ih + (size_t)(bn * 128 + r) * EO + kt + seg * 4);
            Bs[seg * 4 + 0][r] = b4.x;
            Bs[seg * 4 + 1][r] = b4.y;
            Bs[seg * 4 + 2][r] = b4.z;
            Bs[seg * 4 + 3][r] = b4.w;
        }
        __syncthreads();
        #pragma unroll
        for (int kk = 0; kk < 16; kk++) {
            float4 av0 = *(const float4*)&As[kk][ty * 8];
            float4 av1 = *(const float4*)&As[kk][ty * 8 + 4];
            ulonglong2 b01 = *(const ulonglong2*)&Bs[kk][tx * 8];
            ulonglong2 b23 = *(const ulonglong2*)&Bs[kk][tx * 8 + 4];
            ull a;
            a = pack2(av0.x, av0.x); fma2(acc[0][0], a, b01.x); fma2(acc[0][1], a, b01.y); fma2(acc[0][2], a, b23.x); fma2(acc[0][3], a, b23.y);
            a = pack2(av0.y, av0.y); fma2(acc[1][0], a, b01.x); fma2(acc[1][1], a, b01.y); fma2(acc[1][2], a, b23.x); fma2(acc[1][3], a, b23.y);
            a = pack2(av0.z, av0.z); fma2(acc[2][0], a, b01.x); fma2(acc[2][1], a, b01.y); fma2(acc[2][2], a, b23.x); fma2(acc[2][3], a, b23.y);
            a = pack2(av0.w, av0.w); fma2(acc[3][0], a, b01.x); fma2(acc[3][1], a, b01.y); fma2(acc[3][2], a, b23.x); fma2(acc[3][3], a, b23.y);
            a = pack2(av1.x, av1.x); fma2(acc[4][0], a, b01.x); fma2(acc[4][1], a, b01.y); fma2(acc[4][2], a, b23.x); fma2(acc[4][3], a, b23.y);
            a = pack2(av1.y, av1.y); fma2(acc[5][0], a, b01.x); fma2(acc[5][1], a, b01.y); fma2(acc[5][2], a, b23.x); fma2(acc[5][3], a, b23.y);
            a = pack2(av1.z, av1.z); fma2(acc[6][0], a, b01.x); fma2(acc[6][1], a, b01.y); fma2(acc[6][2], a, b23.x); fma2(acc[6][3], a, b23.y);
            a = pack2(av1.w, av1.w); fma2(acc[7][0], a, b01.x); fma2(acc[7][1], a, b01.y); fma2(acc[7][2], a, b23.x); fma2(acc[7][3], a, b23.y);
        }
        __syncthreads();
    }
    const int m0 = bm * 128 + ty * 8, n0 = bn * 128 + tx * 8;
    #pragma unroll
    for (int i = 0; i < 8; i++) {
        #pragma unroll
        for (int p = 0; p < 4; p++) {
            float2 v = unpack2(acc[i][p]);
            int n = n0 + p * 2;
            v.x += b_ih[n];
            v.y += b_ih[n + 1];
            *(float2*)&g_xproj[(size_t)(m0 + i) * G3 + n] = v;
        }
    }
}

// ===========================================================================
// GRU: persistent, 128 CTAs x 128 threads. CTA = (bg 0..3, jg 0..31).
// Fused exchange: per-producer flags. Each warp w stages slices p===w (mod 4):
// poll flag[p] (skip own), 1 LDG.cg.128/lane, STS into h buf, release done[p]
// (SMEM tag). Consumers spin on CTA-local done tags, then run the depth-2
// pipelined MAC loop (R12). No monolithic barrier, one L2 trip per step.
// ===========================================================================
#define GRU_NCTA   128
#define GRU_WS     (3 * 128 * 16 * 4)      // floats (96 KB)
#define GRU_HSTR   516
#define GRU_HBUF   (8 * GRU_HSTR)
#define GRU_SMEMB  ((GRU_WS + 2 * GRU_HBUF + 32) * 4)

__global__ __launch_bounds__(128, 1) void gru_kernel(
    const float* __restrict__ W_hh, const float* __restrict__ b_hh,
    const float* __restrict__ W3,   const float* __restrict__ b3,
    float* __restrict__ out)
{
    extern __shared__ __align__(16) float smem[];
    float* w_s = smem;                       // [gate][kq][col16][4]
    float* h_s = smem + GRU_WS;              // [2][8][516]
    u32*   done = (u32*)(smem + GRU_WS + 2 * GRU_HBUF);   // [32] tags

    const int t   = threadIdx.x;
    const int bid = blockIdx.x;
    const int jg  = bid & 31;
    const int bg  = bid >> 5;
    const int w   = t >> 5;                  // warp id 0..3
    const int ln  = t & 31;                  // lane

    // stage W_hh slice, columns swizzled by (kq & 3)
    for (int idx = t; idx < 3 * 16 * 128; idx += 128) {
        int kq = idx & 127;
        int jj = (idx >> 7) & 15;
        int g  = idx >> 11;
        float4 v = *(const float4*)(W_hh + ((size_t)(g * HID + jg * 16 + jj)) * HID + kq * 4);
        int c = (jj + (kq & 3)) & 15;
        *(float4*)(w_s + ((g * 128 + kq) * 16 + c) * 4) = v;
    }
    // zero-init our slice of h buffer 0 (h(-1) = 0) and done tags
    g_h[0][(bg * 8 + (t >> 4)) * HID + jg * 16 + (t & 15)] = 0.0f;
    if (t < 32) done[t] = 0u;
    __syncthreads();
    if (t == 0) st_rel(&g_bflags[bid * 32], 1u);   // "h(-1) ready"

    const u32 done_base = smem_u32(done);

    const int ks = t & 3;
    const int bh = (t >> 2) & 1;
    const int jw = t >> 3;                    // 0..15
    const int jglob = jg * 16 + jw;
    const int bloc  = bh * 4 + ks;
    const int bglob = bg * 8 + bloc;

    const float bhr = b_hh[jglob];
    const float bhz = b_hh[HID + jglob];
    const float bhn = b_hh[2 * HID + jglob];

    const float* wcol = w_s + ((jw + ks) & 15) * 4;

    // producer lane mapping: lane ln -> row r = ln>>2, unit u = ln&3
    const int pr = ln >> 2, pu = ln & 3;

    for (int s = 0; s < SEQ; s++) {
        const float* cur = g_h[s & 1];
        float* nxt = g_h[(s & 1) ^ 1];
        float* hbuf = h_s + (s & 1) * GRU_HBUF;

        // prefetch this step's xproj early
        size_t xb = ((size_t)(s * BAT + bglob)) * G3 + jglob;
        float xr = __ldcg(g_xproj + xb);
        float xz = __ldcg(g_xproj + xb + HID);
        float xn = __ldcg(g_xproj + xb + 2 * HID);

        // ---- PRODUCE: warp w stages slices p = w, w+4, ..., w+28 ----
        #pragma unroll
        for (int k = 0; k < 8; k++) {
            const int p = w + 4 * k;
            if (p != jg) {
                const unsigned* f = &g_bflags[(bg * 32 + p) * 32];
                while (ld_acq(f) < (unsigned)(s + 1)) { }
            }
            float4 v = __ldcg((const float4*)(cur + (size_t)(bg * 8 + pr) * HID + p * 16 + pu * 4));
            *(float4*)(hbuf + pr * GRU_HSTR + p * 16 + pu * 4) = v;
            __syncwarp();
            if (ln == 0) st_rel_sh(done_base + p * 4u, (unsigned)(s + 1));
        }

        // ---- WAIT: all 32 slices staged (CTA-local tags) ----
        {
            u32 da = done_base + (u32)ln * 4u;
            while (ld_acq_sh(da) < (unsigned)(s + 1)) { }
            __syncwarp();
        }

        const float* hbase = hbuf + bh * 4 * GRU_HSTR;

        ull acc[4][3];
        #pragma unroll
        for (int m = 0; m < 4; m++) { acc[m][0] = 0; acc[m][1] = 0; acc[m][2] = 0; }

        // ---- depth-2 register-pipelined MAC loop over 32 k-phases ----
        ulonglong2 wb[2][3], hb[2][4];
        #pragma unroll
        for (int p = 0; p < 2; p++) {
            const int kq = p * 4 + ks;
            const float* wp = wcol + kq * 64;
            wb[p][0] = *(const ulonglong2*)(wp);
            wb[p][1] = *(const ulonglong2*)(wp + 128 * 64);
            wb[p][2] = *(const ulonglong2*)(wp + 2 * 128 * 64);
            const float* hp = hbase + kq * 4;
            #pragma unroll
            for (int m = 0; m < 4; m++)
                hb[p][m] = *(const ulonglong2*)(hp + m * GRU_HSTR);
        }
        #pragma unroll 2
        for (int i = 0; i < 32; i++) {
            const int c = i & 1;
            #pragma unroll
            for (int m = 0; m < 4; m++) {
                fma2(acc[m][0], hb[c][m].x, wb[c][0].x); fma2(acc[m][0], hb[c][m].y, wb[c][0].y);
                fma2(acc[m][1], hb[c][m].x, wb[c][1].x); fma2(acc[m][1], hb[c][m].y, wb[c][1].y);
                fma2(acc[m][2], hb[c][m].x, wb[c][2].x); fma2(acc[m][2], hb[c][m].y, wb[c][2].y);
            }
            if (i + 2 < 32) {
                const int kq = (i + 2) * 4 + ks;
                const float* wp = wcol + kq * 64;
                wb[c][0] = *(const ulonglong2*)(wp);
                wb[c][1] = *(const ulonglong2*)(wp + 128 * 64);
                wb[c][2] = *(const ulonglong2*)(wp + 2 * 128 * 64);
                const float* hp = hbase + kq * 4;
                #pragma unroll
                for (int m = 0; m < 4; m++)
                    hb[c][m] = *(const ulonglong2*)(hp + m * GRU_HSTR);
            }
        }

        // collapse f32x2 halves, reduce over the 4 ks lanes (xor 1, 2)
        float sred[4][3];
        #pragma unroll
        for (int m = 0; m < 4; m++)
            #pragma unroll
            for (int g = 0; g < 3; g++) {
                float2 v = unpack2(acc[m][g]);
                sred[m][g] = v.x + v.y;
            }
        #pragma unroll
        for (int off = 1; off <= 2; off <<= 1)
            #pragma unroll
            for (int m = 0; m < 4; m++)
                #pragma unroll
                for (int g = 0; g < 3; g++)
                    sred[m][g] += __shfl_xor_sync(0xffffffffu, sred[m][g], off);

        float ghr = 0.f, ghz = 0.f, ghn = 0.f;
        #pragma unroll
        for (int m = 0; m < 4; m++)
            if (m == ks) { ghr = sred[m][0]; ghz = sred[m][1]; ghn = sred[m][2]; }
        ghr += bhr; ghz += bhz; ghn += bhn;

        float r = fast_sigmoid(xr + ghr);
        float z = fast_sigmoid(xz + ghz);
        float n = fast_tanh(xn + r * ghn);
        float hprev = hbuf[bloc * GRU_HSTR + jglob];
        float hnew  = (1.0f - z) * n + z * hprev;

        nxt[(size_t)bglob * HID + jglob] = hnew;

        // CTA-wide: all stores done -> release our flag for step s+1 consumers
        __syncthreads();
        if (t == 0) st_rel(&g_bflags[bid * 32], (unsigned)(s + 2));
    }

    // ---- head epilogue: need all CTAs' h(SEQ-1) (in g_h[0]) ----
    if (t < 32 && t != jg) {
        const unsigned* f = &g_bflags[(bg * 32 + t) * 32];
        while (ld_acq(f) < (unsigned)(SEQ + 1)) { }
    }
    __syncthreads();
    for (int r = t; r < 8 * 128; r += 128) {
        int rb = r >> 7, rk = r & 127;
        float4 v = __ldcg((const float4*)(g_h[0] + (size_t)(bg * 8 + rb) * HID + rk * 4));
        *(float4*)(h_s + rb * GRU_HSTR + rk * 4) = v;
    }
    __syncthreads();

    {
        const int o  = t & 7;        // 0..7
        const int kc = t >> 3;       // 0..15, k-chunk of 32
        float part[8];
        #pragma unroll
        for (int bb = 0; bb < 8; bb++) part[bb] = 0.f;
        for (int kk = kc * 32; kk < kc * 32 + 32; kk++) {
            float wv = __ldg(W3 + (size_t)kk * OUTD + jg * 8 + o);
            #pragma unroll
            for (int bb = 0; bb < 8; bb++)
                part[bb] = fmaf(h_s[bb * GRU_HSTR + kk], wv, part[bb]);
        }
        float* red = w_s;  // scratch [16][8][8]
        #pragma unroll
        for (int bb = 0; bb < 8; bb++) red[(kc * 8 + o) * 8 + bb] = part[bb];
        __syncthreads();
        if (t < 64) {
            int oo = t & 7, bb = t >> 3;
            float sum = b3[jg * 8 + oo];
            #pragma unroll
            for (int k2 = 0; k2 < 16; k2++) sum += red[(k2 * 8 + oo) * 8 + bb];
            out[(bg * 8 + bb) * OUTD + jg * 8 + oo] = sum;
        }
    }

    // ---- flag reset handshake (next graph replay must see zeros) ----
    __syncthreads();
    if (t == 0) st_rel(&g_bflags[bid * 32], (unsigned)(SEQ + 2));
    if (jg == 0) {
        if (t < 32) {
            const unsigned* f = &g_bflags[(bg * 32 + t) * 32];
            while (ld_acq(f) < (unsigned)(SEQ + 2)) { }
        }
        __syncthreads();
        if (t < 32) *(volatile unsigned*)&g_bflags[(bg * 32 + t) * 32] = 0u;
    }
}

// ===========================================================================
extern "C" void kernel_launch(void* const* d_in, const int* in_sizes, int n_in,
                              void* d_out, int out_size)
{
    const int*   input = (const int*)  d_in[0];
    const float* W1    = (const float*)d_in[1];
    const float* b1    = (const float*)d_in[2];
    const float* W2    = (const float*)d_in[3];
    const float* b2    = (const float*)d_in[4];
    const float* W_ih  = (const float*)d_in[5];
    const float* W_hh  = (const float*)d_in[6];
    const float* b_ih  = (const float*)d_in[7];
    const float* b_hh  = (const float*)d_in[8];
    const float* W3    = (const float*)d_in[9];
    const float* b3    = (const float*)d_in[10];
    float* out = (float*)d_out;

    static int configured = 0;
    if (!configured) {
        cudaFuncSetAttribute(gru_kernel,
            cudaFuncAttributeMaxDynamicSharedMemorySize, GRU_SMEMB);
        configured = 1;
    }

    dim3 g1(MROWS / 128, EO / 64);
    gemm_embed_kernel<<<g1, 256>>>(input, W1, b1, W2, b2);

    // xproj split into two N-halves so gru_kernel is the 4th launch per call
    dim3 g2(MROWS / 128, G3 / 128 / 2);
    gemm_xproj_kernel<<<g2, 256>>>(W_ih, b_ih, 0);
    gemm_xproj_kernel<<<g2, 256>>>(W_ih, b_ih, G3 / 128 / 2);

    gru_kernel<<<GRU_NCTA, 128, GRU_SMEMB>>>(W_hh, b_hh, W3, b3, out);
}

// round 15
// speedup vs baseline: 1.8434x; 1.8434x over previous
#include <cuda_runtime.h>
#include <cuda_bf16.h>
#include <cstdint>
#include <math.h>

#define SEQ   128
#define BAT   32
#define EH    512
#define EO    256
#define HID   512
#define G3    1536
#define OUTD  256
#define MROWS (SEQ*BAT)
#define THRESH 1e-6f

typedef unsigned long long ull;
typedef unsigned int u32;

// ---------------- scratch (device globals; no allocation allowed) ----------
__device__ float g_emb[MROWS * EO];          // 4 MB
__device__ float g_xproj[MROWS * G3];        // 25 MB
__device__ float g_h[2][BAT * HID];          // ping-pong hidden state
// per-CTA barrier flags (leaderless all-to-all within each bg group of 32)
__device__ __align__(128) unsigned g_bflags[128 * 32]; // flag per CTA, 128B apart

// ---------------- f32x2 helpers -------------------------------------------
__device__ __forceinline__ ull pack2(float lo, float hi) {
    ull r; asm("mov.b64 %0, {%1, %2};" : "=l"(r) : "f"(lo), "f"(hi)); return r;
}
__device__ __forceinline__ float2 unpack2(ull v) {
    float2 r; asm("mov.b64 {%0, %1}, %2;" : "=f"(r.x), "=f"(r.y) : "l"(v)); return r;
}
__device__ __forceinline__ void fma2(ull& d, ull a, ull b) {
    asm("fma.rn.f32x2 %0, %1, %2, %3;" : "=l"(d) : "l"(a), "l"(b), "l"(d));
}
__device__ __forceinline__ float thr(float v) { return v > THRESH ? v : 0.0f; }

// fast gates: MUFU-based sigmoid / tanh (no libm slow paths)
__device__ __forceinline__ float fast_sigmoid(float x) {
    float e = __expf(-x);
    return __fdividef(1.0f, 1.0f + e);
}
__device__ __forceinline__ float fast_tanh(float x) {
    float e = __expf(-2.0f * x);
    return __fdividef(1.0f - e, 1.0f + e);
}

// ---------------- acquire/release helpers ----------------------------------
__device__ __forceinline__ unsigned ld_acq(const unsigned* p) {
    unsigned v; asm volatile("ld.acquire.gpu.u32 %0, [%1];" : "=r"(v) : "l"(p)); return v;
}
__device__ __forceinline__ void st_rel(unsigned* p, unsigned v) {
    asm volatile("st.release.gpu.u32 [%0], %1;" :: "l"(p), "r"(v));
}

// ===========================================================================
// GEMM 1 (fused embedding): emb = thr( thr(W1[tok]+b1) @ W2 + b2 )
//   M=4096 K=512 N=256. Tile 64x64x16, 256 threads, 4x4 micro-tile (f32x2).
//   64-row tiles -> grid = 64x4 = 256 CTAs (~2 CTAs/SM; was grid-limited).
// ===========================================================================
__global__ __launch_bounds__(256) void gemm_embed_kernel(
    const int* __restrict__ tok, const float* __restrict__ W1,
    const float* __restrict__ b1, const float* __restrict__ W2,
    const float* __restrict__ b2)
{
    __shared__ __align__(16) float As[16][68];
    __shared__ __align__(16) float Bs[16][68];

    const int bm = blockIdx.x, bn = blockIdx.y;
    const int t  = threadIdx.x;
    const int tx = t & 15, ty = t >> 4;

    const int arow = t >> 2, aseg = t & 3;
    const int trow = tok[bm * 64 + arow];
    const float* w1row = W1 + (size_t)trow * EH;
    const int bk = t >> 4, bseg = t & 15;

    ull acc[4][2] = {};

    for (int kt = 0; kt < EH; kt += 16) {
        float4 a4 = *(const float4*)(w1row + kt + aseg * 4);
        float4 bb = *(const float4*)(b1 + kt + aseg * 4);
        a4.x = thr(a4.x + bb.x); a4.y = thr(a4.y + bb.y);
        a4.z = thr(a4.z + bb.z); a4.w = thr(a4.w + bb.w);
        As[aseg * 4 + 0][arow] = a4.x;
        As[aseg * 4 + 1][arow] = a4.y;
        As[aseg * 4 + 2][arow] = a4.z;
        As[aseg * 4 + 3][arow] = a4.w;
        *(float4*)&Bs[bk][bseg * 4] =
            *(const float4*)(W2 + (size_t)(kt + bk) * EO + bn * 64 + bseg * 4);
        __syncthreads();
        #pragma unroll
        for (int kk = 0; kk < 16; kk++) {
            float4 av = *(const float4*)&As[kk][ty * 4];
            ulonglong2 bv = *(const ulonglong2*)&Bs[kk][tx * 4];
            ull a;
            a = pack2(av.x, av.x); fma2(acc[0][0], a, bv.x); fma2(acc[0][1], a, bv.y);
            a = pack2(av.y, av.y); fma2(acc[1][0], a, bv.x); fma2(acc[1][1], a, bv.y);
            a = pack2(av.z, av.z); fma2(acc[2][0], a, bv.x); fma2(acc[2][1], a, bv.y);
            a = pack2(av.w, av.w); fma2(acc[3][0], a, bv.x); fma2(acc[3][1], a, bv.y);
        }
        __syncthreads();
    }
    const int m0 = bm * 64 + ty * 4, n0 = bn * 64 + tx * 4;
    #pragma unroll
    for (int i = 0; i < 4; i++) {
        #pragma unroll
        for (int p = 0; p < 2; p++) {
            float2 v = unpack2(acc[i][p]);
            int n = n0 + p * 2;
            v.x = thr(v.x + b2[n]);
            v.y = thr(v.y + b2[n + 1]);
            *(float2*)&g_emb[(size_t)(m0 + i) * EO + n] = v;
        }
    }
}

// ===========================================================================
// GEMM 2 (NT): xproj = emb @ W_ih^T + b_ih   M=4096 K=256 N=1536
//   Tile 128x128x16, 256 threads, 8x8 micro-tile (f32x2).
//   Launched TWICE (N halves) so gru_kernel stays the 4th launch (profiling).
// ===========================================================================
__global__ __launch_bounds__(256) void gemm_xproj_kernel(
    const float* __restrict__ W_ih, const float* __restrict__ b_ih,
    int bn_off)
{
    __shared__ __align__(16) float As[16][132];
    __shared__ __align__(16) float Bs[16][132];

    const int bm = blockIdx.x, bn = blockIdx.y + bn_off;
    const int t  = threadIdx.x;
    const int tx = t & 15, ty = t >> 4;
    const int row = t >> 2, seg = t & 3;

    ull acc[8][4] = {};

    for (int kt = 0; kt < EO; kt += 16) {
        #pragma unroll
        for (int i = 0; i < 2; i++) {
            int r = row + i * 64;
            float4 a4 = *(const float4*)(g_emb + (size_t)(bm * 128 + r) * EO + kt + seg * 4);
            As[seg * 4 + 0][r] = a4.x;
            As[seg * 4 + 1][r] = a4.y;
            As[seg * 4 + 2][r] = a4.z;
            As[seg * 4 + 3][r] = a4.w;
            float4 b4 = *(const float4*)(W_ih + (size_t)(bn * 128 + r) * EO + kt + seg * 4);
            Bs[seg * 4 + 0][r] = b4.x;
            Bs[seg * 4 + 1][r] = b4.y;
            Bs[seg * 4 + 2][r] = b4.z;
            Bs[seg * 4 + 3][r] = b4.w;
        }
        __syncthreads();
        #pragma unroll
        for (int kk = 0; kk < 16; kk++) {
            float4 av0 = *(const float4*)&As[kk][ty * 8];
            float4 av1 = *(const float4*)&As[kk][ty * 8 + 4];
            ulonglong2 b01 = *(const ulonglong2*)&Bs[kk][tx * 8];
            ulonglong2 b23 = *(const ulonglong2*)&Bs[kk][tx * 8 + 4];
            ull a;
            a = pack2(av0.x, av0.x); fma2(acc[0][0], a, b01.x); fma2(acc[0][1], a, b01.y); fma2(acc[0][2], a, b23.x); fma2(acc[0][3], a, b23.y);
            a = pack2(av0.y, av0.y); fma2(acc[1][0], a, b01.x); fma2(acc[1][1], a, b01.y); fma2(acc[1][2], a, b23.x); fma2(acc[1][3], a, b23.y);
            a = pack2(av0.z, av0.z); fma2(acc[2][0], a, b01.x); fma2(acc[2][1], a, b01.y); fma2(acc[2][2], a, b23.x); fma2(acc[2][3], a, b23.y);
            a = pack2(av0.w, av0.w); fma2(acc[3][0], a, b01.x); fma2(acc[3][1], a, b01.y); fma2(acc[3][2], a, b23.x); fma2(acc[3][3], a, b23.y);
            a = pack2(av1.x, av1.x); fma2(acc[4][0], a, b01.x); fma2(acc[4][1], a, b01.y); fma2(acc[4][2], a, b23.x); fma2(acc[4][3], a, b23.y);
            a = pack2(av1.y, av1.y); fma2(acc[5][0], a, b01.x); fma2(acc[5][1], a, b01.y); fma2(acc[5][2], a, b23.x); fma2(acc[5][3], a, b23.y);
            a = pack2(av1.z, av1.z); fma2(acc[6][0], a, b01.x); fma2(acc[6][1], a, b01.y); fma2(acc[6][2], a, b23.x); fma2(acc[6][3], a, b23.y);
            a = pack2(av1.w, av1.w); fma2(acc[7][0], a, b01.x); fma2(acc[7][1], a, b01.y); fma2(acc[7][2], a, b23.x); fma2(acc[7][3], a, b23.y);
        }
        __syncthreads();
    }
    const int m0 = bm * 128 + ty * 8, n0 = bn * 128 + tx * 8;
    #pragma unroll
    for (int i = 0; i < 8; i++) {
        #pragma unroll
        for (int p = 0; p < 4; p++) {
            float2 v = unpack2(acc[i][p]);
            int n = n0 + p * 2;
            v.x += b_ih[n];
            v.y += b_ih[n + 1];
            *(float2*)&g_xproj[(size_t)(m0 + i) * G3 + n] = v;
        }
    }
}

// ===========================================================================
// GRU recurrence: persistent kernel, 128 CTAs x 128 threads.  (R12 verbatim)
// Leaderless 1-hop barrier + depth-2 register-pipelined MAC loop.
// ===========================================================================
#define GRU_NCTA   128
#define GRU_WS     (3 * 128 * 16 * 4)      // floats (96 KB)
#define GRU_HSTR   516
#define GRU_SMEMB  ((GRU_WS + 8 * GRU_HSTR) * 4)

__global__ __launch_bounds__(128, 1) void gru_kernel(
    const float* __restrict__ W_hh, const float* __restrict__ b_hh,
    const float* __restrict__ W3,   const float* __restrict__ b3,
    float* __restrict__ out)
{
    extern __shared__ __align__(16) float smem[];
    float* w_s = smem;                 // [gate][kq][col16][4], col swizzled
    float* h_s = smem + GRU_WS;        // [8][516]

    const int t   = threadIdx.x;
    const int bid = blockIdx.x;
    const int jg  = bid & 31;
    const int bg  = bid >> 5;

    // stage W_hh slice, columns swizzled by (kq & 3)
    for (int idx = t; idx < 3 * 16 * 128; idx += 128) {
        int kq = idx & 127;
        int jj = (idx >> 7) & 15;
        int g  = idx >> 11;
        float4 v = *(const float4*)(W_hh + ((size_t)(g * HID + jg * 16 + jj)) * HID + kq * 4);
        int c = (jj + (kq & 3)) & 15;
        *(float4*)(w_s + ((g * 128 + kq) * 16 + c) * 4) = v;
    }
    // zero-init our slice of h buffer 0
    g_h[0][(bg * 8 + (t >> 4)) * HID + jg * 16 + (t & 15)] = 0.0f;

    // ---- leaderless per-bg grid barrier: 1 store + 1 direct poll ----
    #define BG_BAR(BI) do {                                                    \
        __syncthreads();                                                       \
        if (t == 0) st_rel(&g_bflags[bid * 32], (unsigned)(BI));               \
        if (t < 32) {                                                          \
            const unsigned* f = &g_bflags[(bg * 32 + t) * 32];                 \
            while (ld_acq(f) < (unsigned)(BI)) { }                             \
        }                                                                      \
        __syncthreads();                                                       \
    } while (0)

    BG_BAR(1);

    const int ks = t & 3;
    const int bh = (t >> 2) & 1;
    const int jw = t >> 3;                    // 0..15
    const int jglob = jg * 16 + jw;
    const int bloc  = bh * 4 + ks;            // local b row this thread outputs
    const int bglob = bg * 8 + bloc;          // global batch row

    const float bhr = b_hh[jglob];
    const float bhz = b_hh[HID + jglob];
    const float bhn = b_hh[2 * HID + jglob];

    const float* wcol = w_s + ((jw + ks) & 15) * 4;  // swizzled column base
    const float* hbase = h_s + bh * 4 * GRU_HSTR;

    for (int step = 0; step < SEQ; step++) {
        const float* cur = g_h[step & 1];
        float* nxt = g_h[(step & 1) ^ 1];

        // prefetch this step's xproj early (hide latency behind restage+MMA)
        size_t xb = ((size_t)(step * BAT + bglob)) * G3 + jglob;
        float xr = __ldcg(g_xproj + xb);
        float xz = __ldcg(g_xproj + xb + HID);
        float xn = __ldcg(g_xproj + xb + 2 * HID);

        // restage h slice (written by other SMs -> bypass L1)
        for (int r = t; r < 8 * 128; r += 128) {
            int rb = r >> 7, rk = r & 127;
            float4 v = __ldcg((const float4*)(cur + (size_t)(bg * 8 + rb) * HID + rk * 4));
            *(float4*)(h_s + rb * GRU_HSTR + rk * 4) = v;
        }
        __syncthreads();

        ull acc[4][3];
        #pragma unroll
        for (int m = 0; m < 4; m++) { acc[m][0] = 0; acc[m][1] = 0; acc[m][2] = 0; }

        // ---- depth-2 register-pipelined MAC loop over 32 k-phases ----
        ulonglong2 wb[2][3], hb[2][4];
        #pragma unroll
        for (int p = 0; p < 2; p++) {
            const int kq = p * 4 + ks;
            const float* wp = wcol + kq * 64;
            wb[p][0] = *(const ulonglong2*)(wp);
            wb[p][1] = *(const ulonglong2*)(wp + 128 * 64);
            wb[p][2] = *(const ulonglong2*)(wp + 2 * 128 * 64);
            const float* hp = hbase + kq * 4;
            #pragma unroll
            for (int m = 0; m < 4; m++)
                hb[p][m] = *(const ulonglong2*)(hp + m * GRU_HSTR);
        }
        #pragma unroll 2
        for (int i = 0; i < 32; i++) {
            const int c = i & 1;
            #pragma unroll
            for (int m = 0; m < 4; m++) {
                fma2(acc[m][0], hb[c][m].x, wb[c][0].x); fma2(acc[m][0], hb[c][m].y, wb[c][0].y);
                fma2(acc[m][1], hb[c][m].x, wb[c][1].x); fma2(acc[m][1], hb[c][m].y, wb[c][1].y);
                fma2(acc[m][2], hb[c][m].x, wb[c][2].x); fma2(acc[m][2], hb[c][m].y, wb[c][2].y);
            }
            if (i + 2 < 32) {
                const int kq = (i + 2) * 4 + ks;
                const float* wp = wcol + kq * 64;
                wb[c][0] = *(const ulonglong2*)(wp);
                wb[c][1] = *(const ulonglong2*)(wp + 128 * 64);
                wb[c][2] = *(const ulonglong2*)(wp + 2 * 128 * 64);
                const float* hp = hbase + kq * 4;
                #pragma unroll
                for (int m = 0; m < 4; m++)
                    hb[c][m] = *(const ulonglong2*)(hp + m * GRU_HSTR);
            }
        }

        // collapse f32x2 halves, reduce over the 4 ks lanes (xor 1, 2)
        float s[4][3];
        #pragma unroll
        for (int m = 0; m < 4; m++)
            #pragma unroll
            for (int g = 0; g < 3; g++) {
                float2 v = unpack2(acc[m][g]);
                s[m][g] = v.x + v.y;
            }
        #pragma unroll
        for (int off = 1; off <= 2; off <<= 1)
            #pragma unroll
            for (int m = 0; m < 4; m++)
                #pragma unroll
                for (int g = 0; g < 3; g++)
                    s[m][g] += __shfl_xor_sync(0xffffffffu, s[m][g], off);

        // thread finalizes b-index m == ks (predicated select)
        float ghr = 0.f, ghz = 0.f, ghn = 0.f;
        #pragma unroll
        for (int m = 0; m < 4; m++)
            if (m == ks) { ghr = s[m][0]; ghz = s[m][1]; ghn = s[m][2]; }
        ghr += bhr; ghz += bhz; ghn += bhn;

        float r = fast_sigmoid(xr + ghr);
        float z = fast_sigmoid(xz + ghz);
        float n = fast_tanh(xn + r * ghn);
        float hprev = h_s[bloc * GRU_HSTR + jglob];
        float hnew  = (1.0f - z) * n + z * hprev;

        nxt[(size_t)bglob * HID + jglob] = hnew;
        BG_BAR(step + 2);
    }

    // ---- head epilogue: out[b][o] = h[b] . W3[:,o] + b3[o] ----
    // CTA covers b in [bg*8,+8), o in [jg*8,+8). SEQ even -> h in g_h[0].
    for (int r = t; r < 8 * 128; r += 128) {
        int rb = r >> 7, rk = r & 127;
        float4 v = __ldcg((const float4*)(g_h[0] + (size_t)(bg * 8 + rb) * HID + rk * 4));
        *(float4*)(h_s + rb * GRU_HSTR + rk * 4) = v;
    }
    __syncthreads();

    {
        const int o  = t & 7;        // 0..7
        const int kc = t >> 3;       // 0..15, k-chunk of 32
        float part[8];
        #pragma unroll
        for (int bb = 0; bb < 8; bb++) part[bb] = 0.f;
        for (int kk = kc * 32; kk < kc * 32 + 32; kk++) {
            float w = __ldg(W3 + (size_t)kk * OUTD + jg * 8 + o);
            #pragma unroll
            for (int bb = 0; bb < 8; bb++)
                part[bb] = fmaf(h_s[bb * GRU_HSTR + kk], w, part[bb]);
        }
        float* red = w_s;  // scratch [16][8][8] (W no longer needed)
        #pragma unroll
        for (int bb = 0; bb < 8; bb++) red[(kc * 8 + o) * 8 + bb] = part[bb];
        __syncthreads();
        if (t < 64) {
            int oo = t & 7, bb = t >> 3;
            float sum = b3[jg * 8 + oo];
            #pragma unroll
            for (int k2 = 0; k2 < 16; k2++) sum += red[(k2 * 8 + oo) * 8 + bb];
            out[(bg * 8 + bb) * OUTD + jg * 8 + oo] = sum;
        }
    }

    // ---- flag reset handshake (next graph replay must see zeros) ----
    __syncthreads();
    if (t == 0) st_rel(&g_bflags[bid * 32], (unsigned)(SEQ + 3));
    if (jg == 0) {
        if (t < 32) {
            const unsigned* f = &g_bflags[(bg * 32 + t) * 32];
            while (ld_acq(f) < (unsigned)(SEQ + 3)) { }
        }
        __syncthreads();
        if (t < 32) *(volatile unsigned*)&g_bflags[(bg * 32 + t) * 32] = 0u;
    }
}

// ===========================================================================
extern "C" void kernel_launch(void* const* d_in, const int* in_sizes, int n_in,
                              void* d_out, int out_size)
{
    const int*   input = (const int*)  d_in[0];
    const float* W1    = (const float*)d_in[1];
    const float* b1    = (const float*)d_in[2];
    const float* W2    = (const float*)d_in[3];
    const float* b2    = (const float*)d_in[4];
    const float* W_ih  = (const float*)d_in[5];
    const float* W_hh  = (const float*)d_in[6];
    const float* b_ih  = (const float*)d_in[7];
    const float* b_hh  = (const float*)d_in[8];
    const float* W3    = (const float*)d_in[9];
    const float* b3    = (const float*)d_in[10];
    float* out = (float*)d_out;

    static int configured = 0;
    if (!configured) {
        cudaFuncSetAttribute(gru_kernel,
            cudaFuncAttributeMaxDynamicSharedMemorySize, GRU_SMEMB);
        configured = 1;
    }

    // 64-row tiles -> 256 CTAs (~2/SM) instead of 128 (grid-limited)
    dim3 g1(MROWS / 64, EO / 64);
    gemm_embed_kernel<<<g1, 256>>>(input, W1, b1, W2, b2);

    // xproj split into two N-halves so gru_kernel is the 4th launch per call
    dim3 g2(MROWS / 128, G3 / 128 / 2);
    gemm_xproj_kernel<<<g2, 256>>>(W_ih, b_ih, 0);
    gemm_xproj_kernel<<<g2, 256>>>(W_ih, b_ih, G3 / 128 / 2);

    gru_kernel<<<GRU_NCTA, 128, GRU_SMEMB>>>(W_hh, b_hh, W3, b3, out);
}

// round 16
// speedup vs baseline: 1.8883x; 1.0244x over previous
#include <cuda_runtime.h>
#include <cuda_bf16.h>
#include <cstdint>
#include <math.h>

#define SEQ   128
#define BAT   32
#define EH    512
#define EO    256
#define HID   512
#define G3    1536
#define OUTD  256
#define MROWS (SEQ*BAT)
#define THRESH 1e-6f

typedef unsigned long long ull;
typedef unsigned int u32;

// ---------------- scratch (device globals; no allocation allowed) ----------
__device__ float g_emb[MROWS * EO];          // 4 MB
__device__ float g_xproj[MROWS * G3];        // 25 MB
__device__ float g_h[2][BAT * HID];          // ping-pong hidden state
// per-CTA barrier flags, 128B apart; monotonic in-launch, reset to 0 at end
__device__ __align__(128) unsigned g_bflags[128 * 32];

// ---------------- f32x2 helpers -------------------------------------------
__device__ __forceinline__ ull pack2(float lo, float hi) {
    ull r; asm("mov.b64 %0, {%1, %2};" : "=l"(r) : "f"(lo), "f"(hi)); return r;
}
__device__ __forceinline__ float2 unpack2(ull v) {
    float2 r; asm("mov.b64 {%0, %1}, %2;" : "=f"(r.x), "=f"(r.y) : "l"(v)); return r;
}
__device__ __forceinline__ void fma2(ull& d, ull a, ull b) {
    asm("fma.rn.f32x2 %0, %1, %2, %3;" : "=l"(d) : "l"(a), "l"(b), "l"(d));
}
__device__ __forceinline__ float thr(float v) { return v > THRESH ? v : 0.0f; }

// fast gates: MUFU-based sigmoid / tanh
__device__ __forceinline__ float fast_sigmoid(float x) {
    float e = __expf(-x);
    return __fdividef(1.0f, 1.0f + e);
}
__device__ __forceinline__ float fast_tanh(float x) {
    float e = __expf(-2.0f * x);
    return __fdividef(1.0f - e, 1.0f + e);
}

// ---------------- acquire/release helpers ----------------------------------
__device__ __forceinline__ unsigned ld_acq(const unsigned* p) {
    unsigned v; asm volatile("ld.acquire.gpu.u32 %0, [%1];" : "=r"(v) : "l"(p)); return v;
}
__device__ __forceinline__ void st_rel(unsigned* p, unsigned v) {
    asm volatile("st.release.gpu.u32 [%0], %1;" :: "l"(p), "r"(v));
}

// ===========================================================================
// GEMM 1 (fused embedding): emb = thr( thr(W1[tok]+b1) @ W2 + b2 )
//   M=4096 K=512 N=256. Tile 64x64x16, 256 threads, 4x4 micro-tile (f32x2).
// ===========================================================================
__global__ __launch_bounds__(256) void gemm_embed_kernel(
    const int* __restrict__ tok, const float* __restrict__ W1,
    const float* __restrict__ b1, const float* __restrict__ W2,
    const float* __restrict__ b2)
{
    __shared__ __align__(16) float As[16][68];
    __shared__ __align__(16) float Bs[16][68];

    const int bm = blockIdx.x, bn = blockIdx.y;
    const int t  = threadIdx.x;
    const int tx = t & 15, ty = t >> 4;

    const int arow = t >> 2, aseg = t & 3;
    const int trow = tok[bm * 64 + arow];
    const float* w1row = W1 + (size_t)trow * EH;
    const int bk = t >> 4, bseg = t & 15;

    ull acc[4][2] = {};

    for (int kt = 0; kt < EH; kt += 16) {
        float4 a4 = *(const float4*)(w1row + kt + aseg * 4);
        float4 bb = *(const float4*)(b1 + kt + aseg * 4);
        a4.x = thr(a4.x + bb.x); a4.y = thr(a4.y + bb.y);
        a4.z = thr(a4.z + bb.z); a4.w = thr(a4.w + bb.w);
        As[aseg * 4 + 0][arow] = a4.x;
        As[aseg * 4 + 1][arow] = a4.y;
        As[aseg * 4 + 2][arow] = a4.z;
        As[aseg * 4 + 3][arow] = a4.w;
        *(float4*)&Bs[bk][bseg * 4] =
            *(const float4*)(W2 + (size_t)(kt + bk) * EO + bn * 64 + bseg * 4);
        __syncthreads();
        #pragma unroll
        for (int kk = 0; kk < 16; kk++) {
            float4 av = *(const float4*)&As[kk][ty * 4];
            ulonglong2 bv = *(const ulonglong2*)&Bs[kk][tx * 4];
            ull a;
            a = pack2(av.x, av.x); fma2(acc[0][0], a, bv.x); fma2(acc[0][1], a, bv.y);
            a = pack2(av.y, av.y); fma2(acc[1][0], a, bv.x); fma2(acc[1][1], a, bv.y);
            a = pack2(av.z, av.z); fma2(acc[2][0], a, bv.x); fma2(acc[2][1], a, bv.y);
            a = pack2(av.w, av.w); fma2(acc[3][0], a, bv.x); fma2(acc[3][1], a, bv.y);
        }
        __syncthreads();
    }
    const int m0 = bm * 64 + ty * 4, n0 = bn * 64 + tx * 4;
    #pragma unroll
    for (int i = 0; i < 4; i++) {
        #pragma unroll
        for (int p = 0; p < 2; p++) {
            float2 v = unpack2(acc[i][p]);
            int n = n0 + p * 2;
            v.x = thr(v.x + b2[n]);
            v.y = thr(v.y + b2[n + 1]);
            *(float2*)&g_emb[(size_t)(m0 + i) * EO + n] = v;
        }
    }
}

// ===========================================================================
// GEMM 2 (NT): xproj = emb @ W_ih^T + b_ih   M=4096 K=256 N=1536
//   Tile 128x128x16, 256 threads, 8x8 micro-tile (f32x2). Two N-half launches.
// ===========================================================================
__global__ __launch_bounds__(256) void gemm_xproj_kernel(
    const float* __restrict__ W_ih, const float* __restrict__ b_ih,
    int bn_off)
{
    __shared__ __align__(16) float As[16][132];
    __shared__ __align__(16) float Bs[16][132];

    const int bm = blockIdx.x, bn = blockIdx.y + bn_off;
    const int t  = threadIdx.x;
    const int tx = t & 15, ty = t >> 4;
    const int row = t >> 2, seg = t & 3;

    ull acc[8][4] = {};

    for (int kt = 0; kt < EO; kt += 16) {
        #pragma unroll
        for (int i = 0; i < 2; i++) {
            int r = row + i * 64;
            float4 a4 = *(const float4*)(g_emb + (size_t)(bm * 128 + r) * EO + kt + seg * 4);
            As[seg * 4 + 0][r] = a4.x;
            As[seg * 4 + 1][r] = a4.y;
            As[seg * 4 + 2][r] = a4.z;
            As[seg * 4 + 3][r] = a4.w;
            float4 b4 = *(const float4*)(W_ih + (size_t)(bn * 128 + r) * EO + kt + seg * 4);
            Bs[seg * 4 + 0][r] = b4.x;
            Bs[seg * 4 + 1][r] = b4.y;
            Bs[seg * 4 + 2][r] = b4.z;
            Bs[seg * 4 + 3][r] = b4.w;
        }
        __syncthreads();
        #pragma unroll
        for (int kk = 0; kk < 16; kk++) {
            float4 av0 = *(const float4*)&As[kk][ty * 8];
            float4 av1 = *(const float4*)&As[kk][ty * 8 + 4];
            ulonglong2 b01 = *(const ulonglong2*)&Bs[kk][tx * 8];
            ulonglong2 b23 = *(const ulonglong2*)&Bs[kk][tx * 8 + 4];
            ull a;
            a = pack2(av0.x, av0.x); fma2(acc[0][0], a, b01.x); fma2(acc[0][1], a, b01.y); fma2(acc[0][2], a, b23.x); fma2(acc[0][3], a, b23.y);
            a = pack2(av0.y, av0.y); fma2(acc[1][0], a, b01.x); fma2(acc[1][1], a, b01.y); fma2(acc[1][2], a, b23.x); fma2(acc[1][3], a, b23.y);
            a = pack2(av0.z, av0.z); fma2(acc[2][0], a, b01.x); fma2(acc[2][1], a, b01.y); fma2(acc[2][2], a, b23.x); fma2(acc[2][3], a, b23.y);
            a = pack2(av0.w, av0.w); fma2(acc[3][0], a, b01.x); fma2(acc[3][1], a, b01.y); fma2(acc[3][2], a, b23.x); fma2(acc[3][3], a, b23.y);
            a = pack2(av1.x, av1.x); fma2(acc[4][0], a, b01.x); fma2(acc[4][1], a, b01.y); fma2(acc[4][2], a, b23.x); fma2(acc[4][3], a, b23.y);
            a = pack2(av1.y, av1.y); fma2(acc[5][0], a, b01.x); fma2(acc[5][1], a, b01.y); fma2(acc[5][2], a, b23.x); fma2(acc[5][3], a, b23.y);
            a = pack2(av1.z, av1.z); fma2(acc[6][0], a, b01.x); fma2(acc[6][1], a, b01.y); fma2(acc[6][2], a, b23.x); fma2(acc[6][3], a, b23.y);
            a = pack2(av1.w, av1.w); fma2(acc[7][0], a, b01.x); fma2(acc[7][1], a, b01.y); fma2(acc[7][2], a, b23.x); fma2(acc[7][3], a, b23.y);
        }
        __syncthreads();
    }
    const int m0 = bm * 128 + ty * 8, n0 = bn * 128 + tx * 8;
    #pragma unroll
    for (int i = 0; i < 8; i++) {
        #pragma unroll
        for (int p = 0; p < 4; p++) {
            float2 v = unpack2(acc[i][p]);
            int n = n0 + p * 2;
            v.x += b_ih[n];
            v.y += b_ih[n + 1];
            *(float2*)&g_xproj[(size_t)(m0 + i) * G3 + n] = v;
        }
    }
}

// ===========================================================================
// GRU: persistent, 128 CTAs x 128 threads. CTA = (bg 0..3, jg 0..31).
// Fused poll+restage, fully parallel: thread t stages slice p=t>>2 (4 threads
// per slice, all 32 slices concurrent): poll flag[p] -> 8 LDG.128 -> STS into
// the double-buffered CTA-private h. Own slice written at gate time (no LDG).
// Monolithic barrier eliminated; MAC loop = R12 depth-2 pipeline.
// ===========================================================================
#define GRU_NCTA   128
#define GRU_WS     (3 * 128 * 16 * 4)      // floats (96 KB)
#define GRU_HSTR   516
#define GRU_HBUF   (8 * GRU_HSTR)
#define GRU_SMEMB  ((GRU_WS + 2 * GRU_HBUF) * 4)

__global__ __launch_bounds__(128, 1) void gru_kernel(
    const float* __restrict__ W_hh, const float* __restrict__ b_hh,
    const float* __restrict__ W3,   const float* __restrict__ b3,
    float* __restrict__ out)
{
    extern __shared__ __align__(16) float smem[];
    float* w_s = smem;                 // [gate][kq][col16][4], col swizzled
    float* h_s = smem + GRU_WS;        // [2][8][516]

    const int t   = threadIdx.x;
    const int bid = blockIdx.x;
    const int jg  = bid & 31;
    const int bg  = bid >> 5;

    // stage W_hh slice, columns swizzled by (kq & 3)
    for (int idx = t; idx < 3 * 16 * 128; idx += 128) {
        int kq = idx & 127;
        int jj = (idx >> 7) & 15;
        int g  = idx >> 11;
        float4 v = *(const float4*)(W_hh + ((size_t)(g * HID + jg * 16 + jj)) * HID + kq * 4);
        int c = (jj + (kq & 3)) & 15;
        *(float4*)(w_s + ((g * 128 + kq) * 16 + c) * 4) = v;
    }
    // zero h buffer 0 (h(-1) = 0); flags are 0 (fresh or reset by prior launch)
    for (int idx = t; idx < GRU_HBUF; idx += 128) h_s[idx] = 0.0f;
    __syncthreads();

    const int ks = t & 3;
    const int bh = (t >> 2) & 1;
    const int jw = t >> 3;                    // 0..15
    const int jglob = jg * 16 + jw;
    const int bloc  = bh * 4 + ks;            // local b row this thread outputs
    const int bglob = bg * 8 + bloc;          // global batch row

    const float bhr = b_hh[jglob];
    const float bhz = b_hh[HID + jglob];
    const float bhn = b_hh[2 * HID + jglob];

    const float* wcol = w_s + ((jw + ks) & 15) * 4;  // swizzled column base

    // restage mapping: thread t -> slice p (t>>2), sub-lane q (t&3) -> rows 2q,2q+1
    const int rp = t >> 2, rq = t & 3;
    const unsigned* rflag = &g_bflags[(bg * 32 + rp) * 32];

    for (int step = 0; step < SEQ; step++) {
        const float* hbuf = h_s + (step & 1) * GRU_HBUF;
        float* hnext = h_s + ((step & 1) ^ 1) * GRU_HBUF;
        float* nxt = g_h[(step & 1) ^ 1];

        // prefetch this step's xproj early
        size_t xb = ((size_t)(step * BAT + bglob)) * G3 + jglob;
        float xr = __ldcg(g_xproj + xb);
        float xz = __ldcg(g_xproj + xb + HID);
        float xn = __ldcg(g_xproj + xb + 2 * HID);

        const float* hbase = hbuf + bh * 4 * GRU_HSTR;

        ull acc[4][3];
        #pragma unroll
        for (int m = 0; m < 4; m++) { acc[m][0] = 0; acc[m][1] = 0; acc[m][2] = 0; }

        // ---- depth-2 register-pipelined MAC loop over 32 k-phases ----
        ulonglong2 wb[2][3], hb[2][4];
        #pragma unroll
        for (int p = 0; p < 2; p++) {
            const int kq = p * 4 + ks;
            const float* wp = wcol + kq * 64;
            wb[p][0] = *(const ulonglong2*)(wp);
            wb[p][1] = *(const ulonglong2*)(wp + 128 * 64);
            wb[p][2] = *(const ulonglong2*)(wp + 2 * 128 * 64);
            const float* hp = hbase + kq * 4;
            #pragma unroll
            for (int m = 0; m < 4; m++)
                hb[p][m] = *(const ulonglong2*)(hp + m * GRU_HSTR);
        }
        #pragma unroll 2
        for (int i = 0; i < 32; i++) {
            const int c = i & 1;
            #pragma unroll
            for (int m = 0; m < 4; m++) {
                fma2(acc[m][0], hb[c][m].x, wb[c][0].x); fma2(acc[m][0], hb[c][m].y, wb[c][0].y);
                fma2(acc[m][1], hb[c][m].x, wb[c][1].x); fma2(acc[m][1], hb[c][m].y, wb[c][1].y);
                fma2(acc[m][2], hb[c][m].x, wb[c][2].x); fma2(acc[m][2], hb[c][m].y, wb[c][2].y);
            }
            if (i + 2 < 32) {
                const int kq = (i + 2) * 4 + ks;
                const float* wp = wcol + kq * 64;
                wb[c][0] = *(const ulonglong2*)(wp);
                wb[c][1] = *(const ulonglong2*)(wp + 128 * 64);
                wb[c][2] = *(const ulonglong2*)(wp + 2 * 128 * 64);
                const float* hp = hbase + kq * 4;
                #pragma unroll
                for (int m = 0; m < 4; m++)
                    hb[c][m] = *(const ulonglong2*)(hp + m * GRU_HSTR);
            }
        }

        // collapse f32x2 halves, reduce over the 4 ks lanes (xor 1, 2)
        float s[4][3];
        #pragma unroll
        for (int m = 0; m < 4; m++)
            #pragma unroll
            for (int g = 0; g < 3; g++) {
                float2 v = unpack2(acc[m][g]);
                s[m][g] = v.x + v.y;
            }
        #pragma unroll
        for (int off = 1; off <= 2; off <<= 1)
            #pragma unroll
            for (int m = 0; m < 4; m++)
                #pragma unroll
                for (int g = 0; g < 3; g++)
                    s[m][g] += __shfl_xor_sync(0xffffffffu, s[m][g], off);

        float ghr = 0.f, ghz = 0.f, ghn = 0.f;
        #pragma unroll
        for (int m = 0; m < 4; m++)
            if (m == ks) { ghr = s[m][0]; ghz = s[m][1]; ghn = s[m][2]; }
        ghr += bhr; ghz += bhz; ghn += bhn;

        float r = fast_sigmoid(xr + ghr);
        float z = fast_sigmoid(xz + ghz);
        float n = fast_tanh(xn + r * ghn);
        float hprev = hbuf[bloc * GRU_HSTR + jglob];
        float hnew  = (1.0f - z) * n + z * hprev;

        // own value: global (for peers) + directly into next local buffer
        nxt[(size_t)bglob * HID + jglob] = hnew;
        hnext[bloc * GRU_HSTR + jglob] = hnew;

        __syncthreads();   // all global h stores issued; own slice in hnext
        if (t == 0) st_rel(&g_bflags[bid * 32], (unsigned)(step + 2));

        // ---- fused poll+restage: slice rp (skip own), rows 2rq, 2rq+1 ----
        if (rp != jg) {
            while (ld_acq(rflag) < (unsigned)(step + 2)) { }
            #pragma unroll
            for (int rr = 0; rr < 2; rr++) {
                const int row = 2 * rq + rr;
                const float* src = nxt + (size_t)(bg * 8 + row) * HID + rp * 16;
                float* dst = hnext + row * GRU_HSTR + rp * 16;
                #pragma unroll
                for (int f4 = 0; f4 < 4; f4++) {
                    float4 v = __ldcg((const float4*)(src + f4 * 4));
                    *(float4*)(dst + f4 * 4) = v;
                }
            }
        }
        __syncthreads();   // hnext complete for next step's MAC
    }

    // ---- head epilogue: h(SEQ-1) is fully resident in h_s buffer 0 ----
    {
        const float* hf = h_s;        // SEQ even -> final h in buffer 0
        const int o  = t & 7;         // 0..7
        const int kc = t >> 3;        // 0..15, k-chunk of 32
        float part[8];
        #pragma unroll
        for (int bb = 0; bb < 8; bb++) part[bb] = 0.f;
        for (int kk = kc * 32; kk < kc * 32 + 32; kk++) {
            float w = __ldg(W3 + (size_t)kk * OUTD + jg * 8 + o);
            #pragma unroll
            for (int bb = 0; bb < 8; bb++)
                part[bb] = fmaf(hf[bb * GRU_HSTR + kk], w, part[bb]);
        }
        float* red = w_s;  // scratch [16][8][8] (W no longer needed)
        #pragma unroll
        for (int bb = 0; bb < 8; bb++) red[(kc * 8 + o) * 8 + bb] = part[bb];
        __syncthreads();
        if (t < 64) {
            int oo = t & 7, bb = t >> 3;
            float sum = b3[jg * 8 + oo];
            #pragma unroll
            for (int k2 = 0; k2 < 16; k2++) sum += red[(k2 * 8 + oo) * 8 + bb];
            out[(bg * 8 + bb) * OUTD + jg * 8 + oo] = sum;
        }
    }

    // ---- flag reset handshake (next graph replay must see zeros) ----
    // After a CTA sets SEQ+3 it never reads group flags again.
    __syncthreads();
    if (t == 0) st_rel(&g_bflags[bid * 32], (unsigned)(SEQ + 3));
    if (jg == 0) {
        if (t < 32) {
            const unsigned* f = &g_bflags[(bg * 32 + t) * 32];
            while (ld_acq(f) < (unsigned)(SEQ + 3)) { }
        }
        __syncthreads();
        if (t < 32) *(volatile unsigned*)&g_bflags[(bg * 32 + t) * 32] = 0u;
    }
}

// ===========================================================================
extern "C" void kernel_launch(void* const* d_in, const int* in_sizes, int n_in,
                              void* d_out, int out_size)
{
    const int*   input = (const int*)  d_in[0];
    const float* W1    = (const float*)d_in[1];
    const float* b1    = (const float*)d_in[2];
    const float* W2    = (const float*)d_in[3];
    const float* b2    = (const float*)d_in[4];
    const float* W_ih  = (const float*)d_in[5];
    const float* W_hh  = (const float*)d_in[6];
    const float* b_ih  = (const float*)d_in[7];
    const float* b_hh  = (const float*)d_in[8];
    const float* W3    = (const float*)d_in[9];
    const float* b3    = (const float*)d_in[10];
    float* out = (float*)d_out;

    static int configured = 0;
    if (!configured) {
        cudaFuncSetAttribute(gru_kernel,
            cudaFuncAttributeMaxDynamicSharedMemorySize, GRU_SMEMB);
        configured = 1;
    }

    dim3 g1(MROWS / 64, EO / 64);
    gemm_embed_kernel<<<g1, 256>>>(input, W1, b1, W2, b2);

    // xproj split into two N-halves so gru_kernel is the 4th launch per call
    dim3 g2(MROWS / 128, G3 / 128 / 2);
    gemm_xproj_kernel<<<g2, 256>>>(W_ih, b_ih, 0);
    gemm_xproj_kernel<<<g2, 256>>>(W_ih, b_ih, G3 / 128 / 2);

    gru_kernel<<<GRU_NCTA, 128, GRU_SMEMB>>>(W_hh, b_hh, W3, b3, out);
}